// round 7
// baseline (speedup 1.0000x reference)
#include <cuda_runtime.h>
#include <cstdint>

// CausalConv1d: x (4, 2048, 8192) f32, depthwise weight (2048, 1, 16), bias (2048)
// out[n,c,l] = sum_{k=0..15} x[n,c,l-15+k] * w[c,0,k] + bias[c]   (zero-pad left)
//
// Persistent-block TMA ring: grid = 592 (one resident wave, 4 blocks/SM).
// Each block owns an 8-slot smem ring (1040 floats/slot) and streams ~14 rows
// through it. tid 0 keeps up to 8 cp.async.bulk tiles in flight continuously
// (full barrier = complete_tx, empty barrier = 8 warp arrives). No wave
// transitions, no per-block pipeline restart.

#define DIM    2048
#define LEN    8192
#define KSZ    16
#define BLOCK  256
#define OPT    4
#define TILE   (BLOCK * OPT)        // 1024
#define TPR    (LEN / TILE)         // 8 tiles per row
#define NSLOT  8
#define STAGEF (TILE + KSZ)         // 1040 floats
#define NROWS  (4 * DIM)            // 8192
#define GRID   592                  // 4 blocks x 148 SMs

__device__ __forceinline__ uint32_t smem_u32(const void* p) {
    return (uint32_t)__cvta_generic_to_shared(p);
}
__device__ __forceinline__ void mbar_init(uint32_t mbar, uint32_t count) {
    asm volatile("mbarrier.init.shared.b64 [%0], %1;" :: "r"(mbar), "r"(count) : "memory");
}
__device__ __forceinline__ void mbar_arrive(uint32_t mbar) {
    asm volatile("mbarrier.arrive.release.cta.shared::cta.b64 _, [%0];" :: "r"(mbar) : "memory");
}
__device__ __forceinline__ void mbar_expect_tx(uint32_t mbar, uint32_t bytes) {
    asm volatile("mbarrier.arrive.expect_tx.release.cta.shared::cta.b64 _, [%0], %1;"
                 :: "r"(mbar), "r"(bytes) : "memory");
}
__device__ __forceinline__ void bulk_g2s(uint32_t dst, const void* src,
                                         uint32_t bytes, uint32_t mbar) {
    asm volatile(
        "cp.async.bulk.shared::cta.global.mbarrier::complete_tx::bytes [%0], [%1], %2, [%3];"
        :: "r"(dst), "l"(src), "r"(bytes), "r"(mbar) : "memory");
}
__device__ __forceinline__ void mbar_wait(uint32_t mbar, uint32_t parity) {
    uint32_t done;
    asm volatile(
        "{\n\t.reg .pred p;\n\t"
        "mbarrier.try_wait.parity.acquire.cta.shared::cta.b64 p, [%1], %2;\n\t"
        "selp.b32 %0, 1, 0, p;\n\t}"
        : "=r"(done) : "r"(mbar), "r"(parity) : "memory");
    if (!done) {
        asm volatile(
            "{\n\t.reg .pred P1;\n\t"
            "WAIT_LOOP_%=:\n\t"
            "mbarrier.try_wait.parity.acquire.cta.shared::cta.b64 P1, [%0], %1, 0x989680;\n\t"
            "@P1 bra.uni WAIT_DONE_%=;\n\t"
            "bra.uni WAIT_LOOP_%=;\n\t"
            "WAIT_DONE_%=:\n\t}"
            :: "r"(mbar), "r"(parity) : "memory");
    }
}

__global__ __launch_bounds__(BLOCK, 4) void causal_conv1d_kernel(
    const float* __restrict__ x,
    const float* __restrict__ w,
    const float* __restrict__ bias,
    float* __restrict__ out)
{
    __shared__ alignas(128) float slot[NSLOT][STAGEF];
    __shared__ alignas(8)   unsigned long long fullb[NSLOT];
    __shared__ alignas(8)   unsigned long long emptyb[NSLOT];

    const int tid  = threadIdx.x;
    const int lane = tid & 31;
    const int bid  = blockIdx.x;
    const int grid = gridDim.x;

    if (tid < NSLOT) {
        mbar_init(smem_u32(&fullb[tid]), 1);
        mbar_init(smem_u32(&emptyb[tid]), 8);   // one arrive per warp
    }
    __syncthreads();
    if (tid == 0) asm volatile("fence.proxy.async.shared::cta;" ::: "memory");

    const int nrows = (NROWS - bid + grid - 1) / grid;   // rows this block handles
    const int T = nrows * TPR;                           // total tiles

    // producer: issue tile t into slot t&7 (slot must already be free)
    auto issue = [&](int t) {
        const int ri  = t >> 3;                 // row index within this block
        const int s   = t & 7;                  // tile within row
        const int si  = t & 7;                  // slot (== s since TPR == NSLOT)
        const int row = bid + ri * grid;
        const float* xrow = x + (size_t)row * LEN;
        if (s == 0) {
            // zero the 16-float left pad, then TMA the 1024 data floats
            float4 z = make_float4(0.f, 0.f, 0.f, 0.f);
            float4* p = reinterpret_cast<float4*>(&slot[si][0]);
            p[0] = z; p[1] = z; p[2] = z; p[3] = z;
            mbar_expect_tx(smem_u32(&fullb[si]), TILE * 4);
            bulk_g2s(smem_u32(&slot[si][KSZ]), xrow, TILE * 4, smem_u32(&fullb[si]));
        } else {
            mbar_expect_tx(smem_u32(&fullb[si]), STAGEF * 4);
            bulk_g2s(smem_u32(&slot[si][0]), xrow + s * TILE - KSZ,
                     STAGEF * 4, smem_u32(&fullb[si]));
        }
    };

    // prologue: fill the ring
    if (tid == 0) {
        const int npro = (T < NSLOT) ? T : NSLOT;
        for (int t = 0; t < npro; t++) issue(t);
    }

    float wr[KSZ];
    float b = 0.f;

    for (int t = 0; t < T; t++) {
        const int ri = t >> 3;
        const int s  = t & 7;
        const int si = t & 7;
        const uint32_t par = (uint32_t)((t >> 3) & 1);

        if (s == 0) {
            // new row: (re)load weights + bias (warp-uniform, overlaps TMA)
            const int row = bid + ri * grid;
            const int ch  = row & (DIM - 1);
            const float4* w4 = reinterpret_cast<const float4*>(w + ch * KSZ);
            #pragma unroll
            for (int q = 0; q < 4; q++) {
                float4 tt = w4[q];
                wr[4 * q + 0] = tt.x; wr[4 * q + 1] = tt.y;
                wr[4 * q + 2] = tt.z; wr[4 * q + 3] = tt.w;
            }
            b = bias[ch];
        }

        mbar_wait(smem_u32(&fullb[si]), par);

        // window r[i] = slot[si][4*tid + i], 5 conflict-free LDS.128
        float r[OPT + KSZ];
        const float4* sp = reinterpret_cast<const float4*>(&slot[si][4 * tid]);
        #pragma unroll
        for (int q = 0; q < 5; q++) {
            float4 v = sp[q];
            r[4 * q + 0] = v.x; r[4 * q + 1] = v.y;
            r[4 * q + 2] = v.z; r[4 * q + 3] = v.w;
        }

        // slot data is now in registers: release the slot
        __syncwarp();
        if (lane == 0) mbar_arrive(smem_u32(&emptyb[si]));

        float acc[OPT];
        #pragma unroll
        for (int m = 0; m < OPT; m++) {
            float a = b;
            #pragma unroll
            for (int k = 0; k < KSZ; k++)
                a = fmaf(wr[k], r[m + 1 + k], a);
            acc[m] = a;
        }

        const int row = bid + ri * grid;
        float4 o; o.x = acc[0]; o.y = acc[1]; o.z = acc[2]; o.w = acc[3];
        *reinterpret_cast<float4*>(out + (size_t)row * LEN + s * TILE + 4 * tid) = o;

        // producer: refill this slot with tile t+8 once all warps released it
        if (tid == 0 && t + NSLOT < T) {
            mbar_wait(smem_u32(&emptyb[si]), par);
            issue(t + NSLOT);
        }
    }
}

extern "C" void kernel_launch(void* const* d_in, const int* in_sizes, int n_in,
                              void* d_out, int out_size)
{
    const float* x    = (const float*)d_in[0];
    const float* w    = (const float*)d_in[1];
    const float* bias = (const float*)d_in[2];
    float* out        = (float*)d_out;

    causal_conv1d_kernel<<<GRID, BLOCK>>>(x, w, bias, out);
}

// round 8
// speedup vs baseline: 1.0046x; 1.0046x over previous
#include <cuda_runtime.h>
#include <cstdint>

// CausalConv1d: x (4, 2048, 8192) f32, depthwise weight (2048, 1, 16), bias (2048)
// out[n,c,l] = sum_{k=0..15} x[n,c,l-15+k] * w[c,0,k] + bias[c]   (zero-pad left)
//
// Persistent blocks (444 = 3/SM) with row ping-pong: two 8-stage slot sets
// (66.5 KB smem). At the top of row j, tid0 bursts all 8 cp.async.bulk tiles
// of row j+1 into the other set (safe: that set was drained before the
// __syncthreads ending row j-1). Consumers then process row j's 8 stages with
// static unrolled indices, R6-style: 5 conflict-free LDS.128 + 64 FMA + STG.128.
// No wave transitions, no per-tile ring logic, TMA latency hidden by a full
// row of compute.

#define DIM    2048
#define LEN    8192
#define KSZ    16
#define BLOCK  256
#define OPT    4
#define TILE   (BLOCK * OPT)        // 1024
#define TPR    (LEN / TILE)         // 8 stages per row
#define STAGEF (TILE + KSZ)         // 1040 floats
#define NROWS  (4 * DIM)            // 8192
#define GRID   444                  // 3 blocks x 148 SMs

__device__ __forceinline__ uint32_t smem_u32(const void* p) {
    return (uint32_t)__cvta_generic_to_shared(p);
}
__device__ __forceinline__ void mbar_init(uint32_t mbar, uint32_t count) {
    asm volatile("mbarrier.init.shared.b64 [%0], %1;" :: "r"(mbar), "r"(count) : "memory");
}
__device__ __forceinline__ void mbar_expect_tx(uint32_t mbar, uint32_t bytes) {
    asm volatile("mbarrier.arrive.expect_tx.release.cta.shared::cta.b64 _, [%0], %1;"
                 :: "r"(mbar), "r"(bytes) : "memory");
}
__device__ __forceinline__ void bulk_g2s(uint32_t dst, const void* src,
                                         uint32_t bytes, uint32_t mbar) {
    asm volatile(
        "cp.async.bulk.shared::cta.global.mbarrier::complete_tx::bytes [%0], [%1], %2, [%3];"
        :: "r"(dst), "l"(src), "r"(bytes), "r"(mbar) : "memory");
}
__device__ __forceinline__ void mbar_wait(uint32_t mbar, uint32_t parity) {
    uint32_t done;
    asm volatile(
        "{\n\t.reg .pred p;\n\t"
        "mbarrier.try_wait.parity.acquire.cta.shared::cta.b64 p, [%1], %2;\n\t"
        "selp.b32 %0, 1, 0, p;\n\t}"
        : "=r"(done) : "r"(mbar), "r"(parity) : "memory");
    if (!done) {
        asm volatile(
            "{\n\t.reg .pred P1;\n\t"
            "WAIT_LOOP_%=:\n\t"
            "mbarrier.try_wait.parity.acquire.cta.shared::cta.b64 P1, [%0], %1, 0x989680;\n\t"
            "@P1 bra.uni WAIT_DONE_%=;\n\t"
            "bra.uni WAIT_LOOP_%=;\n\t"
            "WAIT_DONE_%=:\n\t}"
            :: "r"(mbar), "r"(parity) : "memory");
    }
}

__global__ __launch_bounds__(BLOCK, 3) void causal_conv1d_kernel(
    const float* __restrict__ x,
    const float* __restrict__ w,
    const float* __restrict__ bias,
    float* __restrict__ out)
{
    __shared__ alignas(128) float slot[2][TPR][STAGEF];
    __shared__ alignas(8)   unsigned long long fullb[2][TPR];

    const int tid  = threadIdx.x;
    const int bid  = blockIdx.x;
    const int grid = gridDim.x;

    // init: barriers + the 16-float zero pad of stage 0 in BOTH sets
    // (stage-0 TMA never touches [0,16), so the pad stays zero forever).
    if (tid < 2 * TPR) mbar_init(smem_u32(&fullb[tid >> 3][tid & 7]), 1);
    if (tid < 2 * (KSZ / 4)) {
        float4 z = make_float4(0.f, 0.f, 0.f, 0.f);
        *reinterpret_cast<float4*>(&slot[tid >> 2][0][4 * (tid & 3)]) = z;
    }
    __syncthreads();
    if (tid == 0) asm volatile("fence.proxy.async.shared::cta;" ::: "memory");

    const int nrows = (NROWS - 1 - bid) / grid + 1;   // rows for this block

    // burst-issue all 8 stages of a row into set `set` with parity baked in
    auto issue_row = [&](int row, int set) {
        const float* xrow = x + (size_t)row * LEN;
        mbar_expect_tx(smem_u32(&fullb[set][0]), TILE * 4);
        bulk_g2s(smem_u32(&slot[set][0][KSZ]), xrow, TILE * 4, smem_u32(&fullb[set][0]));
        #pragma unroll
        for (int s = 1; s < TPR; s++) {
            mbar_expect_tx(smem_u32(&fullb[set][s]), STAGEF * 4);
            bulk_g2s(smem_u32(&slot[set][s][0]), xrow + s * TILE - KSZ,
                     STAGEF * 4, smem_u32(&fullb[set][s]));
        }
    };

    // prologue: row 0 into set 0
    if (tid == 0) issue_row(bid, 0);

    for (int j = 0; j < nrows; j++) {
        const int set = j & 1;
        const uint32_t par = (uint32_t)((j >> 1) & 1);
        const int row = bid + j * grid;
        const int ch  = row & (DIM - 1);

        // prefetch next row into the other set (drained before last row's
        // closing __syncthreads; for j==0 the set is untouched).
        if (tid == 0 && j + 1 < nrows)
            issue_row(bid + (j + 1) * grid, set ^ 1);

        // weights + bias for this row (warp-uniform; overlaps TMA)
        float wr[KSZ];
        const float4* w4 = reinterpret_cast<const float4*>(w + ch * KSZ);
        #pragma unroll
        for (int q = 0; q < 4; q++) {
            float4 t = w4[q];
            wr[4 * q + 0] = t.x; wr[4 * q + 1] = t.y;
            wr[4 * q + 2] = t.z; wr[4 * q + 3] = t.w;
        }
        const float b = bias[ch];

        float* __restrict__ orow = out + (size_t)row * LEN;

        #pragma unroll
        for (int s = 0; s < TPR; s++) {
            mbar_wait(smem_u32(&fullb[set][s]), par);

            // window r[i] = slot[set][s][4*tid + i]: 5 conflict-free LDS.128
            float r[OPT + KSZ];
            const float4* sp = reinterpret_cast<const float4*>(&slot[set][s][4 * tid]);
            #pragma unroll
            for (int q = 0; q < 5; q++) {
                float4 v = sp[q];
                r[4 * q + 0] = v.x; r[4 * q + 1] = v.y;
                r[4 * q + 2] = v.z; r[4 * q + 3] = v.w;
            }

            float acc[OPT];
            #pragma unroll
            for (int m = 0; m < OPT; m++) {
                float a = b;
                #pragma unroll
                for (int k = 0; k < KSZ; k++)
                    a = fmaf(wr[k], r[m + 1 + k], a);
                acc[m] = a;
            }

            float4 o; o.x = acc[0]; o.y = acc[1]; o.z = acc[2]; o.w = acc[3];
            *reinterpret_cast<float4*>(orow + s * TILE + 4 * tid) = o;
        }

        // all warps done with set `set` -> next iteration may refill it
        __syncthreads();
    }
}

extern "C" void kernel_launch(void* const* d_in, const int* in_sizes, int n_in,
                              void* d_out, int out_size)
{
    const float* x    = (const float*)d_in[0];
    const float* w    = (const float*)d_in[1];
    const float* bias = (const float*)d_in[2];
    float* out        = (float*)d_out;

    causal_conv1d_kernel<<<GRID, BLOCK>>>(x, w, bias, out);
}

// round 9
// speedup vs baseline: 1.1769x; 1.1716x over previous
#include <cuda_runtime.h>
#include <cstdint>

// CausalConv1d: x (4, 2048, 8192) f32, depthwise weight (2048, 1, 16), bias (2048)
// out[n,c,l] = sum_{k=0..15} x[n,c,l-15+k] * w[c,0,k] + bias[c]   (zero-pad left)
//
// R6 structure (proven best): one block per row, tid 0 bursts all 8
// cp.async.bulk tiles up front (per-stage complete_tx mbarrier), consumers do
// 5 conflict-free LDS.128 + 64 FMA + STG.128 per stage. This round: raise
// residency to 5 blocks/SM (smem 166KB/228KB, regs<=51 no spill) so staggered
// blocks hide each other's prologue latency and mbarrier waits.

#define DIM    2048
#define LEN    8192
#define KSZ    16
#define BLOCK  256
#define OPT    4
#define TILE   (BLOCK * OPT)      // 1024
#define NST    (LEN / TILE)       // 8 stages
#define STAGEF (TILE + KSZ)       // 1040 floats per stage
#define STAGEB (STAGEF * 4)       // 4160 bytes

__device__ __forceinline__ uint32_t smem_u32(const void* p) {
    return (uint32_t)__cvta_generic_to_shared(p);
}

__device__ __forceinline__ void mbar_init(uint32_t mbar, uint32_t count) {
    asm volatile("mbarrier.init.shared.b64 [%0], %1;" :: "r"(mbar), "r"(count) : "memory");
}

__device__ __forceinline__ void mbar_expect_tx(uint32_t mbar, uint32_t bytes) {
    asm volatile("mbarrier.arrive.expect_tx.shared.b64 _, [%0], %1;"
                 :: "r"(mbar), "r"(bytes) : "memory");
}

__device__ __forceinline__ void bulk_g2s(uint32_t dst, const void* src,
                                         uint32_t bytes, uint32_t mbar) {
    asm volatile(
        "cp.async.bulk.shared::cta.global.mbarrier::complete_tx::bytes [%0], [%1], %2, [%3];"
        :: "r"(dst), "l"(src), "r"(bytes), "r"(mbar) : "memory");
}

__device__ __forceinline__ void mbar_wait_parity0(uint32_t mbar) {
    uint32_t done;
    asm volatile(
        "{\n\t.reg .pred p;\n\t"
        "mbarrier.try_wait.parity.acquire.cta.shared::cta.b64 p, [%1], 0;\n\t"
        "selp.b32 %0, 1, 0, p;\n\t}"
        : "=r"(done) : "r"(mbar) : "memory");
    if (!done) {
        asm volatile(
            "{\n\t.reg .pred P1;\n\t"
            "WAIT_LOOP_%=:\n\t"
            "mbarrier.try_wait.parity.acquire.cta.shared::cta.b64 P1, [%0], 0, 0x989680;\n\t"
            "@P1 bra.uni WAIT_DONE_%=;\n\t"
            "bra.uni WAIT_LOOP_%=;\n\t"
            "WAIT_DONE_%=:\n\t}"
            :: "r"(mbar) : "memory");
    }
}

__global__ __launch_bounds__(BLOCK, 5) void causal_conv1d_kernel(
    const float* __restrict__ x,
    const float* __restrict__ w,
    const float* __restrict__ bias,
    float* __restrict__ out)
{
    __shared__ alignas(128) float stage[NST][STAGEF];
    __shared__ alignas(8)   unsigned long long mbar[NST];

    const int tid = threadIdx.x;
    const int row = blockIdx.x;
    const int ch  = row & (DIM - 1);             // row = n*DIM + c

    const float* __restrict__ xrow = x   + (size_t)row * LEN;
    float*       __restrict__ orow = out + (size_t)row * LEN;

    // ---- init barriers + zero the 16-float left pad of stage 0 ----
    if (tid < NST) mbar_init(smem_u32(&mbar[tid]), 1);
    if (tid < KSZ / 4) {
        float4 z = make_float4(0.f, 0.f, 0.f, 0.f);
        *reinterpret_cast<float4*>(&stage[0][4 * tid]) = z;
    }
    __syncthreads();

    // ---- producer: prefetch all 8 stages immediately (tid 0) ----
    if (tid == 0) {
        asm volatile("fence.proxy.async.shared::cta;" ::: "memory");
        // stage 0: data starts at offset 16 (halo is the zero pad)
        mbar_expect_tx(smem_u32(&mbar[0]), TILE * 4);
        bulk_g2s(smem_u32(&stage[0][KSZ]), xrow, TILE * 4, smem_u32(&mbar[0]));
        #pragma unroll
        for (int s = 1; s < NST; s++) {
            mbar_expect_tx(smem_u32(&mbar[s]), STAGEB);
            bulk_g2s(smem_u32(&stage[s][0]), xrow + s * TILE - KSZ,
                     STAGEB, smem_u32(&mbar[s]));
        }
    }

    // ---- weights + bias (warp-uniform, overlaps TMA) ----
    float wr[KSZ];
    const float4* w4 = reinterpret_cast<const float4*>(w + ch * KSZ);
    #pragma unroll
    for (int q = 0; q < 4; q++) {
        float4 t = w4[q];
        wr[4 * q + 0] = t.x; wr[4 * q + 1] = t.y;
        wr[4 * q + 2] = t.z; wr[4 * q + 3] = t.w;
    }
    const float b = bias[ch];

    // ---- consume stage by stage ----
    #pragma unroll
    for (int s = 0; s < NST; s++) {
        mbar_wait_parity0(smem_u32(&mbar[s]));

        // window r[i] = xrow[s*TILE - 16 + 4*tid + i] = stage[s][4*tid + i]
        float r[OPT + KSZ];
        const float4* sp = reinterpret_cast<const float4*>(&stage[s][4 * tid]);
        #pragma unroll
        for (int q = 0; q < 5; q++) {
            float4 v = sp[q];
            r[4 * q + 0] = v.x; r[4 * q + 1] = v.y;
            r[4 * q + 2] = v.z; r[4 * q + 3] = v.w;
        }

        float acc[OPT];
        #pragma unroll
        for (int m = 0; m < OPT; m++) {
            float a = b;
            #pragma unroll
            for (int k = 0; k < KSZ; k++)
                a = fmaf(wr[k], r[m + 1 + k], a);
            acc[m] = a;
        }

        float4 o; o.x = acc[0]; o.y = acc[1]; o.z = acc[2]; o.w = acc[3];
        *reinterpret_cast<float4*>(orow + s * TILE + 4 * tid) = o;
    }
}

extern "C" void kernel_launch(void* const* d_in, const int* in_sizes, int n_in,
                              void* d_out, int out_size)
{
    const float* x    = (const float*)d_in[0];
    const float* w    = (const float*)d_in[1];
    const float* bias = (const float*)d_in[2];
    float* out        = (float*)d_out;

    const int blocks = 4 * DIM;                  // 8192 rows
    causal_conv1d_kernel<<<blocks, BLOCK>>>(x, w, bias, out);
}